// round 9
// baseline (speedup 1.0000x reference)
#include <cuda_runtime.h>
#include <cuda_bf16.h>
#include <cstdint>

// ---------------------------------------------------------------------------
// SpatialConvModule (SCNN-style): 4 directional recurrent 3-tap convs + fusion
// B=8, C=128, H=W=160. All fp32, packed f32x2 FMA (sm_103a).
// R8: 4-line fused recurrence steps (40 launches), pre/feat split buffers.
// ---------------------------------------------------------------------------

#define EPSV 1e-5f
#define SPAT 25600            // 160*160

// ---- static device scratch (allocation-free rule) -------------------------
__device__ float  g_pre [4ull*8*128*160*160];  // pre-activations (read-only in steps)
__device__ float  g_feat[4ull*8*128*160*160];  // recurrence outputs (features)
__device__ float  g_xT [8ull*128*160*160];     // x transposed per (b,c): [w][h]
__device__ float  g_tmp[2ull*8*128*160*160];   // dirs 2,3 feat transposed back
__device__ float2 g_wkp[4*64*3*128];           // [dir][cpair][tap][o] (even,odd c)
__device__ float2 g_wfp[256*128];              // [qpair][o], pre-scaled by fbn inv
__device__ float  g_s[512], g_sh[512], g_fc[128];

// packed fp32x2 fma: d = a*b + c (elementwise on both halves)
__device__ __forceinline__ float2 ffma2f(float2 a, float2 b, float2 c) {
    float2 d;
    asm("fma.rn.f32x2 %0, %1, %2, %3;"
        : "=l"(reinterpret_cast<unsigned long long&>(d))
        : "l"(reinterpret_cast<unsigned long long&>(a)),
          "l"(reinterpret_cast<unsigned long long&>(b)),
          "l"(reinterpret_cast<unsigned long long&>(c)));
    return d;
}

// tiny no-op used to shift ncu's -s 5 -c 1 capture window onto pre_kernel
__global__ void noop_kernel() {}

// ---------------------------------------------------------------------------
// Prep: repack conv weights to [dir][cpair][tap][o] float2, fold BN into
// scale/shift, pre-scale fusion weights by fused-BN inv.
// ---------------------------------------------------------------------------
__global__ void prep_kernel(const float* __restrict__ kern,
                            const float* __restrict__ bg, const float* __restrict__ bb,
                            const float* __restrict__ bm, const float* __restrict__ bv,
                            const float* __restrict__ fw, const float* __restrict__ fb,
                            const float* __restrict__ fg, const float* __restrict__ fbeta,
                            const float* __restrict__ fm, const float* __restrict__ fv) {
    const int NWK = 98304, NWF = 32768;
    int total = NWK + NWF + 512 + 128;
    for (int i = blockIdx.x * blockDim.x + threadIdx.x; i < total;
         i += gridDim.x * blockDim.x) {
        if (i < NWK) {
            int dir = i / 24576; int r = i % 24576;
            int cp = r / 384;    int r2 = r % 384;
            int d = r2 / 128;    int o = r2 % 128;
            int c0 = 2 * cp;
            float a0, a1;
            if (dir < 2) {  // 1x3 kernel: kh=1, kw=d
                a0 = kern[(((dir*128 + o)*128 + c0    )*3 + 1)*3 + d];
                a1 = kern[(((dir*128 + o)*128 + c0 + 1)*3 + 1)*3 + d];
            } else {        // 3x1 kernel: kh=d, kw=1
                a0 = kern[(((dir*128 + o)*128 + c0    )*3 + d)*3 + 1];
                a1 = kern[(((dir*128 + o)*128 + c0 + 1)*3 + d)*3 + 1];
            }
            g_wkp[i] = make_float2(a0, a1);
        } else if (i < NWK + NWF) {
            int idx = i - NWK; int qp = idx / 128; int o = idx % 128;
            float fs = fg[o] * rsqrtf(fv[o] + EPSV);
            g_wfp[idx] = make_float2(fw[o*512 + 2*qp] * fs, fw[o*512 + 2*qp + 1] * fs);
        } else if (i < NWK + NWF + 512) {
            int idx = i - NWK - NWF;
            float s = bg[idx] * rsqrtf(bv[idx] + EPSV);
            g_s[idx] = s; g_sh[idx] = bb[idx] - bm[idx] * s;
        } else {
            int o = i - NWK - NWF - 512;
            float fs = fg[o] * rsqrtf(fv[o] + EPSV);
            g_fc[o] = fb[o] * fs + fbeta[o] - fm[o] * fs;
        }
    }
}

// ---------------------------------------------------------------------------
// Tiled 160x160 transpose, M independent matrices.
// mode 0: src_x -> g_xT (M = 8*128)
// mode 1: g_feat[dirs 2,3] -> g_tmp (M = 2*8*128)
// ---------------------------------------------------------------------------
__global__ void transpose_kernel(const float* __restrict__ src_x, int mode) {
    __shared__ float t[32][33];
    int m  = blockIdx.x / 25;
    int tl = blockIdx.x % 25;
    int r0 = (tl / 5) * 32, c0 = (tl % 5) * 32;
    const float* s;
    float* d;
    if (mode == 0) { s = src_x  + (size_t)m * SPAT;              d = g_xT  + (size_t)m * SPAT; }
    else           { s = g_feat + (size_t)(16*128 + m) * SPAT;   d = g_tmp + (size_t)m * SPAT; }
    int x = threadIdx.x;
    for (int y = threadIdx.y; y < 32; y += 8)
        t[y][x] = s[(r0 + y) * 160 + c0 + x];
    __syncthreads();
    for (int y = threadIdx.y; y < 32; y += 8)
        d[(c0 + y) * 160 + r0 + x] = t[x][y];
}

// ---------------------------------------------------------------------------
// Pre kernel (all 4 dirs unified): out[line][p] = bias + sum_{c,d} in[c][line][p-1+d]*K
// Rows dirs read x (line=h, p=w); cols dirs read g_xT (line=w, p=h).
// Block: 128 threads (one output channel each) x 32 positions.
// ---------------------------------------------------------------------------
__global__ void __launch_bounds__(128) pre_kernel(const float* __restrict__ x,
                                                  const float* __restrict__ biases) {
    int bx   = blockIdx.x;          // 25600 = 4*8*160*5
    int tile = bx % 5;
    int line = (bx / 5) % 160;
    int b    = (bx / 800) % 8;
    int dir  = bx / 6400;
    int o    = threadIdx.x;
    int p0   = tile * 32;

    const float* src = ((dir < 2) ? x : g_xT) + (size_t)(b * 128) * SPAT;
    __shared__ float sb[34 * 18];   // [p(34)][c(16)], stride 18 (8B-aligned pairs)

    float2 acc[32];
#pragma unroll
    for (int j = 0; j < 32; ++j) acc[j] = make_float2(0.f, 0.f);

    const float2* wbase = g_wkp + dir * 24576;

    for (int c0 = 0; c0 < 128; c0 += 16) {
        for (int i = threadIdx.x; i < 16 * 34; i += 128) {
            int c = i / 34, pp = i % 34;
            int pos = p0 - 1 + pp;
            float v = 0.f;
            if (pos >= 0 && pos < 160)
                v = src[(size_t)(c0 + c) * SPAT + line * 160 + pos];
            sb[pp * 18 + c] = v;
        }
        __syncthreads();
        for (int cp = 0; cp < 8; ++cp) {
            const float2* wp = wbase + ((c0 >> 1) + cp) * 384 + o;
            float2 k0 = wp[0], k1 = wp[128], k2 = wp[256];
            float2 v0 = *reinterpret_cast<const float2*>(sb + 0 * 18 + 2 * cp);
            float2 v1 = *reinterpret_cast<const float2*>(sb + 1 * 18 + 2 * cp);
#pragma unroll
            for (int j = 0; j < 32; ++j) {
                float2 v2 = *reinterpret_cast<const float2*>(sb + (j + 2) * 18 + 2 * cp);
                acc[j] = ffma2f(v0, k0, acc[j]);
                acc[j] = ffma2f(v1, k1, acc[j]);
                acc[j] = ffma2f(v2, k2, acc[j]);
                v0 = v1; v1 = v2;
            }
        }
        __syncthreads();
    }

    float bias = biases[dir * 128 + o];
    float* op = g_pre + ((size_t)(dir * 8 + b) * 128 + o) * SPAT + line * 160 + p0;
#pragma unroll
    for (int j4 = 0; j4 < 32; j4 += 4) {
        float4 r;
        r.x = acc[j4    ].x + acc[j4    ].y + bias;
        r.y = acc[j4 + 1].x + acc[j4 + 1].y + bias;
        r.z = acc[j4 + 2].x + acc[j4 + 2].y + bias;
        r.w = acc[j4 + 3].x + acc[j4 + 3].y + bias;
        *reinterpret_cast<float4*>(op + j4) = r;
    }
}

// ---------------------------------------------------------------------------
// Fused 4-line recurrence step. Each launch advances all 4 dirs, 8 batches by
// FOUR scan lines. Halo recompute: line l in the group computes 22-2l
// positions so line l+1's tile-interior conv inputs are all locally available.
// prev line for l=0 comes from g_feat (final, written by previous launch);
// lines 1..3 read the previous line from SMEM ping-pong buffers.
// pre (g_pre) is read-only; y goes to g_feat -> no cross-tile halo races.
// Grid: 4 dirs * 8 b * 10 tiles = 320 blocks of 128 threads.
// ---------------------------------------------------------------------------
__global__ void __launch_bounds__(128) step4_kernel(const float* __restrict__ prelu_a,
                                                    int g) {
    int bx   = blockIdx.x;
    int tile = bx % 10;
    int b    = (bx / 10) % 8;
    int dir  = bx / 80;
    int o    = threadIdx.x;
    int p0   = tile * 16;
    int base = p0 - 4;                     // buffer idx t <-> global pos base+t

    bool fwd = (dir == 0) || (dir == 2);
    const float* pb = g_pre  + (size_t)(dir * 8 + b) * 128 * SPAT;
    float*       yb = g_feat + (size_t)(dir * 8 + b) * 128 * SPAT;

    __shared__ float buf0[24 * 128];
    __shared__ float buf1[24 * 128];
    float* sprev = buf0;
    float* scur  = buf1;

    int s0 = 4 * g;
    // stage y of line (s0-1) from gmem (zeros for g==0 / out-of-range)
    {
        int sp = s0 - 1;
        int Lp = fwd ? sp : 159 - sp;
        const float* pr = yb + (size_t)o * SPAT + (size_t)(Lp < 0 ? 0 : Lp) * 160;
#pragma unroll
        for (int t = 0; t < 24; ++t) {
            int gp = base + t;
            float v = 0.f;
            if (g > 0 && gp >= 0 && gp < 160) v = pr[gp];
            sprev[t * 128 + o] = v;
        }
    }
    __syncthreads();

    float s  = g_s [dir * 128 + o];
    float sh = g_sh[dir * 128 + o];
    float a  = prelu_a[dir];
    const float2* wbase = g_wkp + dir * 24576;

#pragma unroll
    for (int l = 0; l < 4; ++l) {
        int sidx = s0 + l;
        int L  = fwd ? sidx : 159 - sidx;
        const int np = 22 - 2 * l;         // positions computed this line
        int q0 = p0 - (3 - l);             // global pos of j=0

        float2 acc[22];
#pragma unroll
        for (int j = 0; j < np; ++j) acc[j] = make_float2(0.f, 0.f);

        if (sidx > 0) {
            for (int cp = 0; cp < 64; ++cp) {
                const float2* wp = wbase + cp * 384 + o;
                float2 k0 = wp[0], k1 = wp[128], k2 = wp[256];
                float2 v0 = *reinterpret_cast<const float2*>(sprev + (l    ) * 128 + 2 * cp);
                float2 v1 = *reinterpret_cast<const float2*>(sprev + (l + 1) * 128 + 2 * cp);
#pragma unroll
                for (int j = 0; j < np; ++j) {
                    float2 v2 = *reinterpret_cast<const float2*>(sprev + (l + j + 2) * 128 + 2 * cp);
                    acc[j] = ffma2f(v0, k0, acc[j]);
                    acc[j] = ffma2f(v1, k1, acc[j]);
                    acc[j] = ffma2f(v2, k2, acc[j]);
                    v0 = v1; v1 = v2;
                }
            }
        }

        const float* prow = pb + (size_t)o * SPAT + (size_t)L * 160;
        float*       wrow = yb + (size_t)o * SPAT + (size_t)L * 160;
#pragma unroll
        for (int j = 0; j < np; ++j) {
            int gp = q0 + j;
            float y = 0.f;
            if (gp >= 0 && gp < 160) {
                float h = prow[gp] + acc[j].x + acc[j].y;
                y = h * s + sh;
                y = (y >= 0.f) ? y : a * y;
            }
            scur[(1 + l + j) * 128 + o] = y;
            if (j >= 3 - l && j < 19 - l)   // owned window [p0, p0+16)
                wrow[gp] = y;
        }
        __syncthreads();
        float* t_ = sprev; sprev = scur; scur = t_;
    }
}

// ---------------------------------------------------------------------------
// Fusion: out[o] = relu( sum_q feat[q]*wf[q][o]*finv + fc[o] ), q = dir*128+c.
// dirs 0,1 from g_feat (canonical), dirs 2,3 from g_tmp (transposed back).
// ---------------------------------------------------------------------------
__global__ void __launch_bounds__(128) fus_kernel(float* __restrict__ out) {
    int bx   = blockIdx.x;          // 12800 = 8*160*10
    int tile = bx % 10;
    int hh   = (bx / 10) % 160;
    int b    = bx / 1600;
    int t  = threadIdx.x;
    int ol = t & 63;
    int wg = t >> 6;
    int w0 = tile * 16;

    __shared__ float fs[16 * 16];   // [j][c]
    float2 acc0[8], acc1[8];
#pragma unroll
    for (int j = 0; j < 8; ++j) { acc0[j] = make_float2(0.f, 0.f); acc1[j] = make_float2(0.f, 0.f); }

    for (int q0 = 0; q0 < 512; q0 += 16) {
        for (int i = t; i < 256; i += 128) {
            int c = i / 16, j = i % 16;
            int q = q0 + c; int dir = q >> 7; int cc = q & 127;
            const float* fp = (dir < 2)
                ? (g_feat + ((size_t)(dir * 8 + b) * 128 + cc) * SPAT)
                : (g_tmp  + ((size_t)((dir - 2) * 8 + b) * 128 + cc) * SPAT);
            fs[j * 16 + c] = fp[hh * 160 + w0 + j];
        }
        __syncthreads();
        for (int cp = 0; cp < 8; ++cp) {
            int qp = (q0 >> 1) + cp;
            float2 wa = g_wfp[qp * 128 + ol];
            float2 wb = g_wfp[qp * 128 + ol + 64];
#pragma unroll
            for (int jj = 0; jj < 8; ++jj) {
                float2 v = *reinterpret_cast<const float2*>(fs + (wg * 8 + jj) * 16 + 2 * cp);
                acc0[jj] = ffma2f(v, wa, acc0[jj]);
                acc1[jj] = ffma2f(v, wb, acc1[jj]);
            }
        }
        __syncthreads();
    }

    float c0v = g_fc[ol], c1v = g_fc[ol + 64];
    float* ob0 = out + (((size_t)b * 128 + ol     ) * 160 + hh) * 160 + w0 + wg * 8;
    float* ob1 = out + (((size_t)b * 128 + ol + 64) * 160 + hh) * 160 + w0 + wg * 8;
#pragma unroll
    for (int j4 = 0; j4 < 8; j4 += 4) {
        float4 r;
        r.x = fmaxf(acc0[j4    ].x + acc0[j4    ].y + c0v, 0.f);
        r.y = fmaxf(acc0[j4 + 1].x + acc0[j4 + 1].y + c0v, 0.f);
        r.z = fmaxf(acc0[j4 + 2].x + acc0[j4 + 2].y + c0v, 0.f);
        r.w = fmaxf(acc0[j4 + 3].x + acc0[j4 + 3].y + c0v, 0.f);
        *reinterpret_cast<float4*>(ob0 + j4) = r;
        float4 q;
        q.x = fmaxf(acc1[j4    ].x + acc1[j4    ].y + c1v, 0.f);
        q.y = fmaxf(acc1[j4 + 1].x + acc1[j4 + 1].y + c1v, 0.f);
        q.z = fmaxf(acc1[j4 + 2].x + acc1[j4 + 2].y + c1v, 0.f);
        q.w = fmaxf(acc1[j4 + 3].x + acc1[j4 + 3].y + c1v, 0.f);
        *reinterpret_cast<float4*>(ob1 + j4) = q;
    }
}

// ---------------------------------------------------------------------------
extern "C" void kernel_launch(void* const* d_in, const int* in_sizes, int n_in,
                              void* d_out, int out_size) {
    const float* x         = (const float*)d_in[0];
    const float* kernels   = (const float*)d_in[1];
    const float* biases    = (const float*)d_in[2];
    const float* bn_gamma  = (const float*)d_in[3];
    const float* bn_beta   = (const float*)d_in[4];
    const float* bn_mean   = (const float*)d_in[5];
    const float* bn_var    = (const float*)d_in[6];
    const float* prelu_a   = (const float*)d_in[7];
    const float* fus_w     = (const float*)d_in[8];
    const float* fus_b     = (const float*)d_in[9];
    const float* fbn_gamma = (const float*)d_in[10];
    const float* fbn_beta  = (const float*)d_in[11];
    const float* fbn_mean  = (const float*)d_in[12];
    const float* fbn_var   = (const float*)d_in[13];

    prep_kernel<<<128, 256>>>(kernels, bn_gamma, bn_beta, bn_mean, bn_var,
                              fus_w, fus_b, fbn_gamma, fbn_beta, fbn_mean, fbn_var);

    // x -> xT so column directions scan along a contiguous axis
    transpose_kernel<<<8 * 128 * 25, dim3(32, 8)>>>(x, 0);

    // shift ncu's -s 5 -c 1 capture window so launch #6 == pre_kernel
    noop_kernel<<<1, 32>>>();
    noop_kernel<<<1, 32>>>();
    noop_kernel<<<1, 32>>>();

    // pre-activations for all 4 directions
    pre_kernel<<<25600, 128>>>(x, biases);

    // 40 fused recurrence launches; each advances all dirs/batches by 4 lines
    for (int g = 0; g < 40; ++g)
        step4_kernel<<<320, 128>>>(prelu_a, g);

    // bring dirs 2,3 back to canonical [h][w] layout for fusion
    transpose_kernel<<<2 * 8 * 128 * 25, dim3(32, 8)>>>(x, 1);

    // fused 1x1 conv + BN + ReLU
    fus_kernel<<<12800, 128>>>((float*)d_out);
}

// round 10
// speedup vs baseline: 1.0349x; 1.0349x over previous
#include <cuda_runtime.h>
#include <cuda_bf16.h>
#include <cstdint>

// ---------------------------------------------------------------------------
// SpatialConvModule (SCNN-style): 4 directional recurrent 3-tap convs + fusion
// B=8, C=128, H=W=160. All fp32, packed f32x2 FMA (sm_103a).
// R9: weight-prefetch software pipelines (pre/step4/fus); pre split in halves
//     so ncu -s 5 -c 1 captures a pre launch.
// ---------------------------------------------------------------------------

#define EPSV 1e-5f
#define SPAT 25600            // 160*160

// ---- static device scratch (allocation-free rule) -------------------------
__device__ float  g_pre [4ull*8*128*160*160];  // pre-activations (read-only in steps)
__device__ float  g_feat[4ull*8*128*160*160];  // recurrence outputs (features)
__device__ float  g_xT [8ull*128*160*160];     // x transposed per (b,c): [w][h]
__device__ float  g_tmp[2ull*8*128*160*160];   // dirs 2,3 feat transposed back
__device__ float2 g_wkp[4*64*3*128];           // [dir][cpair][tap][o] (even,odd c)
__device__ float2 g_wfp[256*128];              // [qpair][o], pre-scaled by fbn inv
__device__ float  g_s[512], g_sh[512], g_fc[128];

// packed fp32x2 fma: d = a*b + c (elementwise on both halves)
__device__ __forceinline__ float2 ffma2f(float2 a, float2 b, float2 c) {
    float2 d;
    asm("fma.rn.f32x2 %0, %1, %2, %3;"
        : "=l"(reinterpret_cast<unsigned long long&>(d))
        : "l"(reinterpret_cast<unsigned long long&>(a)),
          "l"(reinterpret_cast<unsigned long long&>(b)),
          "l"(reinterpret_cast<unsigned long long&>(c)));
    return d;
}

// tiny no-op used to shift ncu's -s 5 -c 1 capture window onto pre_kernel
__global__ void noop_kernel() {}

// ---------------------------------------------------------------------------
// Prep: repack conv weights to [dir][cpair][tap][o] float2, fold BN into
// scale/shift, pre-scale fusion weights by fused-BN inv.
// ---------------------------------------------------------------------------
__global__ void prep_kernel(const float* __restrict__ kern,
                            const float* __restrict__ bg, const float* __restrict__ bb,
                            const float* __restrict__ bm, const float* __restrict__ bv,
                            const float* __restrict__ fw, const float* __restrict__ fb,
                            const float* __restrict__ fg, const float* __restrict__ fbeta,
                            const float* __restrict__ fm, const float* __restrict__ fv) {
    const int NWK = 98304, NWF = 32768;
    int total = NWK + NWF + 512 + 128;
    for (int i = blockIdx.x * blockDim.x + threadIdx.x; i < total;
         i += gridDim.x * blockDim.x) {
        if (i < NWK) {
            int dir = i / 24576; int r = i % 24576;
            int cp = r / 384;    int r2 = r % 384;
            int d = r2 / 128;    int o = r2 % 128;
            int c0 = 2 * cp;
            float a0, a1;
            if (dir < 2) {  // 1x3 kernel: kh=1, kw=d
                a0 = kern[(((dir*128 + o)*128 + c0    )*3 + 1)*3 + d];
                a1 = kern[(((dir*128 + o)*128 + c0 + 1)*3 + 1)*3 + d];
            } else {        // 3x1 kernel: kh=d, kw=1
                a0 = kern[(((dir*128 + o)*128 + c0    )*3 + d)*3 + 1];
                a1 = kern[(((dir*128 + o)*128 + c0 + 1)*3 + d)*3 + 1];
            }
            g_wkp[i] = make_float2(a0, a1);
        } else if (i < NWK + NWF) {
            int idx = i - NWK; int qp = idx / 128; int o = idx % 128;
            float fs = fg[o] * rsqrtf(fv[o] + EPSV);
            g_wfp[idx] = make_float2(fw[o*512 + 2*qp] * fs, fw[o*512 + 2*qp + 1] * fs);
        } else if (i < NWK + NWF + 512) {
            int idx = i - NWK - NWF;
            float s = bg[idx] * rsqrtf(bv[idx] + EPSV);
            g_s[idx] = s; g_sh[idx] = bb[idx] - bm[idx] * s;
        } else {
            int o = i - NWK - NWF - 512;
            float fs = fg[o] * rsqrtf(fv[o] + EPSV);
            g_fc[o] = fb[o] * fs + fbeta[o] - fm[o] * fs;
        }
    }
}

// ---------------------------------------------------------------------------
// Tiled 160x160 transpose, M independent matrices.
// mode 0: src_x -> g_xT (M = 8*128)
// mode 1: g_feat[dirs 2,3] -> g_tmp (M = 2*8*128)
// ---------------------------------------------------------------------------
__global__ void transpose_kernel(const float* __restrict__ src_x, int mode) {
    __shared__ float t[32][33];
    int m  = blockIdx.x / 25;
    int tl = blockIdx.x % 25;
    int r0 = (tl / 5) * 32, c0 = (tl % 5) * 32;
    const float* s;
    float* d;
    if (mode == 0) { s = src_x  + (size_t)m * SPAT;              d = g_xT  + (size_t)m * SPAT; }
    else           { s = g_feat + (size_t)(16*128 + m) * SPAT;   d = g_tmp + (size_t)m * SPAT; }
    int x = threadIdx.x;
    for (int y = threadIdx.y; y < 32; y += 8)
        t[y][x] = s[(r0 + y) * 160 + c0 + x];
    __syncthreads();
    for (int y = threadIdx.y; y < 32; y += 8)
        d[(c0 + y) * 160 + r0 + x] = t[x][y];
}

// ---------------------------------------------------------------------------
// Pre kernel: out[line][p] = bias + sum_{c,d} in[c][line][p-1+d]*K
// dir0 selects the half: {0,1} read x (line=h, p=w); {2,3} read g_xT.
// Block: 128 threads (one output channel each) x 32 positions.
// Weight loads software-pipelined one cp ahead.
// ---------------------------------------------------------------------------
__global__ void __launch_bounds__(128) pre_kernel(const float* __restrict__ x,
                                                  const float* __restrict__ biases,
                                                  int dir0) {
    int bx   = blockIdx.x;          // 12800 = 2*8*160*5
    int tile = bx % 5;
    int line = (bx / 5) % 160;
    int b    = (bx / 800) % 8;
    int dir  = dir0 + bx / 6400;
    int o    = threadIdx.x;
    int p0   = tile * 32;

    const float* src = ((dir < 2) ? x : g_xT) + (size_t)(b * 128) * SPAT;
    __shared__ float sb[34 * 18];   // [p(34)][c(16)], stride 18 (8B-aligned pairs)

    float2 acc[32];
#pragma unroll
    for (int j = 0; j < 32; ++j) acc[j] = make_float2(0.f, 0.f);

    const float2* wbase = g_wkp + dir * 24576;

    for (int c0 = 0; c0 < 128; c0 += 16) {
        for (int i = threadIdx.x; i < 16 * 34; i += 128) {
            int c = i / 34, pp = i % 34;
            int pos = p0 - 1 + pp;
            float v = 0.f;
            if (pos >= 0 && pos < 160)
                v = src[(size_t)(c0 + c) * SPAT + line * 160 + pos];
            sb[pp * 18 + c] = v;
        }
        __syncthreads();

        const float2* wgrp = wbase + (c0 >> 1) * 384 + o;
        float2 k0 = wgrp[0], k1 = wgrp[128], k2 = wgrp[256];
        for (int cp = 0; cp < 8; ++cp) {
            // prefetch next cp's weights (clamped; in flight during j-loop)
            int ncp = (cp < 7) ? cp + 1 : 7;
            const float2* wn = wgrp + ncp * 384;
            float2 n0 = wn[0], n1 = wn[128], n2 = wn[256];

            float2 v0 = *reinterpret_cast<const float2*>(sb + 0 * 18 + 2 * cp);
            float2 v1 = *reinterpret_cast<const float2*>(sb + 1 * 18 + 2 * cp);
#pragma unroll
            for (int j = 0; j < 32; ++j) {
                float2 v2 = *reinterpret_cast<const float2*>(sb + (j + 2) * 18 + 2 * cp);
                acc[j] = ffma2f(v0, k0, acc[j]);
                acc[j] = ffma2f(v1, k1, acc[j]);
                acc[j] = ffma2f(v2, k2, acc[j]);
                v0 = v1; v1 = v2;
            }
            k0 = n0; k1 = n1; k2 = n2;
        }
        __syncthreads();
    }

    float bias = biases[dir * 128 + o];
    float* op = g_pre + ((size_t)(dir * 8 + b) * 128 + o) * SPAT + line * 160 + p0;
#pragma unroll
    for (int j4 = 0; j4 < 32; j4 += 4) {
        float4 r;
        r.x = acc[j4    ].x + acc[j4    ].y + bias;
        r.y = acc[j4 + 1].x + acc[j4 + 1].y + bias;
        r.z = acc[j4 + 2].x + acc[j4 + 2].y + bias;
        r.w = acc[j4 + 3].x + acc[j4 + 3].y + bias;
        *reinterpret_cast<float4*>(op + j4) = r;
    }
}

// ---------------------------------------------------------------------------
// Fused 4-line recurrence step. Each launch advances all 4 dirs, 8 batches by
// FOUR scan lines with halo recompute (line l computes 22-2l positions).
// prev line for l=0 from g_feat; lines 1..3 from SMEM ping-pong.
// Weight loads software-pipelined TWO cp ahead (depth-2: j-loop ~130cyc < L2).
// Grid: 4 dirs * 8 b * 10 tiles = 320 blocks of 128 threads.
// ---------------------------------------------------------------------------
__global__ void __launch_bounds__(128) step4_kernel(const float* __restrict__ prelu_a,
                                                    int g) {
    int bx   = blockIdx.x;
    int tile = bx % 10;
    int b    = (bx / 10) % 8;
    int dir  = bx / 80;
    int o    = threadIdx.x;
    int p0   = tile * 16;
    int base = p0 - 4;                     // buffer idx t <-> global pos base+t

    bool fwd = (dir == 0) || (dir == 2);
    const float* pb = g_pre  + (size_t)(dir * 8 + b) * 128 * SPAT;
    float*       yb = g_feat + (size_t)(dir * 8 + b) * 128 * SPAT;

    __shared__ float buf0[24 * 128];
    __shared__ float buf1[24 * 128];
    float* sprev = buf0;
    float* scur  = buf1;

    int s0 = 4 * g;
    // stage y of line (s0-1) from gmem (zeros for g==0 / out-of-range)
    {
        int sp = s0 - 1;
        int Lp = fwd ? sp : 159 - sp;
        const float* pr = yb + (size_t)o * SPAT + (size_t)(Lp < 0 ? 0 : Lp) * 160;
#pragma unroll
        for (int t = 0; t < 24; ++t) {
            int gp = base + t;
            float v = 0.f;
            if (g > 0 && gp >= 0 && gp < 160) v = pr[gp];
            sprev[t * 128 + o] = v;
        }
    }
    __syncthreads();

    float s  = g_s [dir * 128 + o];
    float sh = g_sh[dir * 128 + o];
    float a  = prelu_a[dir];
    const float2* wbase = g_wkp + dir * 24576;

#pragma unroll
    for (int l = 0; l < 4; ++l) {
        int sidx = s0 + l;
        int L  = fwd ? sidx : 159 - sidx;
        const int np = 22 - 2 * l;         // positions computed this line
        int q0 = p0 - (3 - l);             // global pos of j=0

        float2 acc[22];
#pragma unroll
        for (int j = 0; j < np; ++j) acc[j] = make_float2(0.f, 0.f);

        if (sidx > 0) {
            // depth-2 weight pipeline
            const float2* wA = wbase + o;
            float2 a0 = wA[0], a1 = wA[128], a2 = wA[256];
            const float2* wB = wbase + 384 + o;
            float2 b0 = wB[0], b1 = wB[128], b2 = wB[256];
            for (int cp = 0; cp < 64; ++cp) {
                int nc = (cp + 2 < 64) ? cp + 2 : 63;
                const float2* wC = wbase + nc * 384 + o;
                float2 c0_ = wC[0], c1_ = wC[128], c2_ = wC[256];

                float2 v0 = *reinterpret_cast<const float2*>(sprev + (l    ) * 128 + 2 * cp);
                float2 v1 = *reinterpret_cast<const float2*>(sprev + (l + 1) * 128 + 2 * cp);
#pragma unroll
                for (int j = 0; j < np; ++j) {
                    float2 v2 = *reinterpret_cast<const float2*>(sprev + (l + j + 2) * 128 + 2 * cp);
                    acc[j] = ffma2f(v0, a0, acc[j]);
                    acc[j] = ffma2f(v1, a1, acc[j]);
                    acc[j] = ffma2f(v2, a2, acc[j]);
                    v0 = v1; v1 = v2;
                }
                a0 = b0; a1 = b1; a2 = b2;
                b0 = c0_; b1 = c1_; b2 = c2_;
            }
        }

        const float* prow = pb + (size_t)o * SPAT + (size_t)L * 160;
        float*       wrow = yb + (size_t)o * SPAT + (size_t)L * 160;
#pragma unroll
        for (int j = 0; j < np; ++j) {
            int gp = q0 + j;
            float y = 0.f;
            if (gp >= 0 && gp < 160) {
                float h = prow[gp] + acc[j].x + acc[j].y;
                y = h * s + sh;
                y = (y >= 0.f) ? y : a * y;
            }
            scur[(1 + l + j) * 128 + o] = y;
            if (j >= 3 - l && j < 19 - l)   // owned window [p0, p0+16)
                wrow[gp] = y;
        }
        __syncthreads();
        float* t_ = sprev; sprev = scur; scur = t_;
    }
}

// ---------------------------------------------------------------------------
// Fusion: out[o] = relu( sum_q feat[q]*wf[q][o]*finv + fc[o] ), q = dir*128+c.
// dirs 0,1 from g_feat (canonical), dirs 2,3 from g_tmp (transposed back).
// Weight loads software-pipelined one cp ahead.
// ---------------------------------------------------------------------------
__global__ void __launch_bounds__(128) fus_kernel(float* __restrict__ out) {
    int bx   = blockIdx.x;          // 12800 = 8*160*10
    int tile = bx % 10;
    int hh   = (bx / 10) % 160;
    int b    = bx / 1600;
    int t  = threadIdx.x;
    int ol = t & 63;
    int wg = t >> 6;
    int w0 = tile * 16;

    __shared__ float fs[16 * 16];   // [j][c]
    float2 acc0[8], acc1[8];
#pragma unroll
    for (int j = 0; j < 8; ++j) { acc0[j] = make_float2(0.f, 0.f); acc1[j] = make_float2(0.f, 0.f); }

    for (int q0 = 0; q0 < 512; q0 += 16) {
        for (int i = t; i < 256; i += 128) {
            int c = i / 16, j = i % 16;
            int q = q0 + c; int dir = q >> 7; int cc = q & 127;
            const float* fp = (dir < 2)
                ? (g_feat + ((size_t)(dir * 8 + b) * 128 + cc) * SPAT)
                : (g_tmp  + ((size_t)((dir - 2) * 8 + b) * 128 + cc) * SPAT);
            fs[j * 16 + c] = fp[hh * 160 + w0 + j];
        }
        __syncthreads();

        int qb = q0 >> 1;
        float2 wa = g_wfp[qb * 128 + ol];
        float2 wb = g_wfp[qb * 128 + ol + 64];
        for (int cp = 0; cp < 8; ++cp) {
            int nqp = qb + ((cp < 7) ? cp + 1 : 7);
            float2 na = g_wfp[nqp * 128 + ol];
            float2 nb = g_wfp[nqp * 128 + ol + 64];
#pragma unroll
            for (int jj = 0; jj < 8; ++jj) {
                float2 v = *reinterpret_cast<const float2*>(fs + (wg * 8 + jj) * 16 + 2 * cp);
                acc0[jj] = ffma2f(v, wa, acc0[jj]);
                acc1[jj] = ffma2f(v, wb, acc1[jj]);
            }
            wa = na; wb = nb;
        }
        __syncthreads();
    }

    float c0v = g_fc[ol], c1v = g_fc[ol + 64];
    float* ob0 = out + (((size_t)b * 128 + ol     ) * 160 + hh) * 160 + w0 + wg * 8;
    float* ob1 = out + (((size_t)b * 128 + ol + 64) * 160 + hh) * 160 + w0 + wg * 8;
#pragma unroll
    for (int j4 = 0; j4 < 8; j4 += 4) {
        float4 r;
        r.x = fmaxf(acc0[j4    ].x + acc0[j4    ].y + c0v, 0.f);
        r.y = fmaxf(acc0[j4 + 1].x + acc0[j4 + 1].y + c0v, 0.f);
        r.z = fmaxf(acc0[j4 + 2].x + acc0[j4 + 2].y + c0v, 0.f);
        r.w = fmaxf(acc0[j4 + 3].x + acc0[j4 + 3].y + c0v, 0.f);
        *reinterpret_cast<float4*>(ob0 + j4) = r;
        float4 q;
        q.x = fmaxf(acc1[j4    ].x + acc1[j4    ].y + c1v, 0.f);
        q.y = fmaxf(acc1[j4 + 1].x + acc1[j4 + 1].y + c1v, 0.f);
        q.z = fmaxf(acc1[j4 + 2].x + acc1[j4 + 2].y + c1v, 0.f);
        q.w = fmaxf(acc1[j4 + 3].x + acc1[j4 + 3].y + c1v, 0.f);
        *reinterpret_cast<float4*>(ob1 + j4) = q;
    }
}

// ---------------------------------------------------------------------------
extern "C" void kernel_launch(void* const* d_in, const int* in_sizes, int n_in,
                              void* d_out, int out_size) {
    const float* x         = (const float*)d_in[0];
    const float* kernels   = (const float*)d_in[1];
    const float* biases    = (const float*)d_in[2];
    const float* bn_gamma  = (const float*)d_in[3];
    const float* bn_beta   = (const float*)d_in[4];
    const float* bn_mean   = (const float*)d_in[5];
    const float* bn_var    = (const float*)d_in[6];
    const float* prelu_a   = (const float*)d_in[7];
    const float* fus_w     = (const float*)d_in[8];
    const float* fus_b     = (const float*)d_in[9];
    const float* fbn_gamma = (const float*)d_in[10];
    const float* fbn_beta  = (const float*)d_in[11];
    const float* fbn_mean  = (const float*)d_in[12];
    const float* fbn_var   = (const float*)d_in[13];

    prep_kernel<<<128, 256>>>(kernels, bn_gamma, bn_beta, bn_mean, bn_var,
                              fus_w, fus_b, fbn_gamma, fbn_beta, fbn_mean, fbn_var);

    // x -> xT so column directions scan along a contiguous axis
    transpose_kernel<<<8 * 128 * 25, dim3(32, 8)>>>(x, 0);

    // pad so ncu's -s 5 -c 1 window lands on a pre half (launch #5 or #6)
    noop_kernel<<<1, 32>>>();
    noop_kernel<<<1, 32>>>();

    // pre-activations, two halves (dirs 0-1, dirs 2-3)
    pre_kernel<<<12800, 128>>>(x, biases, 0);
    pre_kernel<<<12800, 128>>>(x, biases, 2);

    // 40 fused recurrence launches; each advances all dirs/batches by 4 lines
    for (int g = 0; g < 40; ++g)
        step4_kernel<<<320, 128>>>(prelu_a, g);

    // bring dirs 2,3 back to canonical [h][w] layout for fusion
    transpose_kernel<<<2 * 8 * 128 * 25, dim3(32, 8)>>>(x, 1);

    // fused 1x1 conv + BN + ReLU
    fus_kernel<<<12800, 128>>>((float*)d_out);
}